// round 3
// baseline (speedup 1.0000x reference)
#include <cuda_runtime.h>
#include <cuda_fp16.h>
#include <cooperative_groups.h>

namespace cg = cooperative_groups;

#define BB 256
#define TT 2048
#define DD 40
#define HH 128
#define CC 35

// ---------------- device scratch (allocation-free rule: static globals) ----------
__device__ int    g_order[BB];
__device__ int    g_slen[BB];
__device__ __half g_hs1[(size_t)TT * BB * HH];   // layer-0 hidden stream, f16 (128MB)
__device__ float  g_h2[BB * HH];                 // final layer-1 hidden, fp32

// ---------------- helpers --------------------------------------------------------
__device__ __forceinline__ void mma16816(float* d, const unsigned* a, const unsigned* b) {
    asm volatile(
        "mma.sync.aligned.m16n8k16.row.col.f32.f16.f16.f32 "
        "{%0,%1,%2,%3}, {%4,%5,%6,%7}, {%8,%9}, {%0,%1,%2,%3};\n"
        : "+f"(d[0]), "+f"(d[1]), "+f"(d[2]), "+f"(d[3])
        : "r"(a[0]), "r"(a[1]), "r"(a[2]), "r"(a[3]), "r"(b[0]), "r"(b[1]));
}

__device__ __forceinline__ void ldsmx4(unsigned* a, const __half* p) {
    unsigned addr = (unsigned)__cvta_generic_to_shared(p);
    asm volatile("ldmatrix.sync.aligned.m8n8.x4.shared.b16 {%0,%1,%2,%3}, [%4];"
                 : "=r"(a[0]), "=r"(a[1]), "=r"(a[2]), "=r"(a[3])
                 : "r"(addr));
}

__device__ __forceinline__ float sigf(float x)   { return 1.0f / (1.0f + __expf(-x)); }
__device__ __forceinline__ float tanhfa(float x) { return 1.0f - 2.0f / (__expf(2.0f * x) + 1.0f); }

// ---------------- K0: rank-sort lengths (descending, stable) ---------------------
__global__ void sort_kernel(const int* __restrict__ length) {
    __shared__ int len[BB];
    int i = threadIdx.x;
    len[i] = length[i];
    __syncthreads();
    int li = len[i];
    int rank = 0;
    for (int j = 0; j < BB; ++j) {
        int lj = len[j];
        rank += (lj > li) || (lj == li && j < i);
    }
    g_order[rank] = i;
    g_slen[rank]  = li;
}

// ---------------- K1: LSTM layer 0 ------------------------------------------------
// A = [x_t(40) pad->48 | h(128)]  K=176, 11 k-tiles.
// Cluster of 4 CTAs, each CTA: N=128 gate slice (i,f,g,o each 32 h-indices),
// M=16 batch rows, 256 threads (8 warps x N16).
#define KX0 48
#define K0T 176
#define KT0 11

__global__ void __cluster_dims__(4, 1, 1) __launch_bounds__(256, 1)
lstm_l0(const float* __restrict__ x, const float* __restrict__ Wih,
        const float* __restrict__ Whh, const float* __restrict__ bih,
        const float* __restrict__ bhh)
{
    cg::cluster_group cl = cg::this_cluster();
    const int rank  = (int)cl.block_rank();
    const int group = blockIdx.x >> 2;
    const int slotbase = group * 16;
    const int tid  = threadIdx.x;
    const int warp = tid >> 5, lane = tid & 31;

    __shared__ __half Ab[2][16][K0T];
    __shared__ float  gsm[16][128];
    __shared__ float  csm[16][32];
    __shared__ float  bsm[128];
    __shared__ int    slenS[16], morder[16];

    // ---- weight fragments -> registers (one time) ----
    unsigned wf[2][KT0][2];
#pragma unroll
    for (int nt = 0; nt < 2; ++nt) {
        int n_local = warp * 16 + nt * 8 + (lane >> 2);
        int q = n_local >> 5, jj = n_local & 31;
        int grow = q * 128 + rank * 32 + jj;
#pragma unroll
        for (int kt = 0; kt < KT0; ++kt) {
#pragma unroll
            for (int f = 0; f < 2; ++f) {
                int k0 = kt * 16 + (lane & 3) * 2 + f * 8;
                int k1 = k0 + 1;
                float v0 = (k0 < KX0) ? ((k0 < DD) ? Wih[grow * DD + k0] : 0.0f)
                                      : Whh[grow * HH + (k0 - KX0)];
                float v1 = (k1 < KX0) ? ((k1 < DD) ? Wih[grow * DD + k1] : 0.0f)
                                      : Whh[grow * HH + (k1 - KX0)];
                __half2 hv = __floats2half2_rn(v0, v1);
                wf[nt][kt][f] = *reinterpret_cast<unsigned*>(&hv);
            }
        }
    }
    if (tid < 128) {
        int q = tid >> 5, jj = tid & 31;
        int grow = q * 128 + rank * 32 + jj;
        bsm[tid] = bih[grow] + bhh[grow];
    }
    if (tid < 16) {
        slenS[tid]  = g_slen[slotbase + tid];
        morder[tid] = g_order[slotbase + tid];
    }
    for (int i = tid; i < 2 * 16 * K0T; i += 256) ((__half*)Ab)[i] = __float2half(0.0f);
    for (int i = tid; i < 16 * 32;      i += 256) ((float*)csm)[i] = 0.0f;
    __syncthreads();
    const int maxlen = slenS[0];
    // x(0) -> buf 0
    for (int i = tid; i < 16 * DD; i += 256) {
        int m = i / DD, d = i - m * DD;
        Ab[0][m][d] = __float2half(x[((size_t)morder[m] * TT + 0) * DD + d]);
    }
    cl.sync();

    for (int t = 0; t < maxlen; ++t) {
        const int p = t & 1, pn = p ^ 1;
        // prefetch x(t+1) into pn
        if (t + 1 < maxlen) {
            for (int i = tid; i < 16 * DD; i += 256) {
                int m = i / DD, d = i - m * DD;
                Ab[pn][m][d] = __float2half(x[((size_t)morder[m] * TT + (t + 1)) * DD + d]);
            }
        }
        // ---- MMA ----
        float acc[2][4];
        {
            int cb0 = warp * 16 + (lane & 3) * 2;
#pragma unroll
            for (int nt = 0; nt < 2; ++nt) {
                float b0 = bsm[cb0 + nt * 8], b1 = bsm[cb0 + nt * 8 + 1];
                acc[nt][0] = b0; acc[nt][1] = b1; acc[nt][2] = b0; acc[nt][3] = b1;
            }
#pragma unroll
            for (int kt = 0; kt < KT0; ++kt) {
                unsigned a[4];
                ldsmx4(a, &Ab[p][lane & 15][kt * 16 + ((lane >> 4) << 3)]);
                mma16816(acc[0], a, wf[0][kt]);
                mma16816(acc[1], a, wf[1][kt]);
            }
            int r0 = lane >> 2;
#pragma unroll
            for (int nt = 0; nt < 2; ++nt) {
                int c0 = warp * 16 + nt * 8 + (lane & 3) * 2;
                gsm[r0][c0]     = acc[nt][0]; gsm[r0][c0 + 1]     = acc[nt][1];
                gsm[r0 + 8][c0] = acc[nt][2]; gsm[r0 + 8][c0 + 1] = acc[nt][3];
            }
        }
        __syncthreads();
        // ---- pointwise + h broadcast ----
        {
            int m = tid >> 4, jl = (tid & 15) * 2;
            bool act = (t < slenS[m]);
            __half2 hv;
            if (act) {
                float i0 = sigf(gsm[m][jl]),        i1 = sigf(gsm[m][jl + 1]);
                float f0 = sigf(gsm[m][32 + jl]),   f1 = sigf(gsm[m][32 + jl + 1]);
                float q0 = tanhfa(gsm[m][64 + jl]), q1 = tanhfa(gsm[m][64 + jl + 1]);
                float o0 = sigf(gsm[m][96 + jl]),   o1 = sigf(gsm[m][96 + jl + 1]);
                float c0 = f0 * csm[m][jl]     + i0 * q0;
                float c1 = f1 * csm[m][jl + 1] + i1 * q1;
                csm[m][jl] = c0; csm[m][jl + 1] = c1;
                hv = __floats2half2_rn(o0 * tanhfa(c0), o1 * tanhfa(c1));
            } else {
                hv = *reinterpret_cast<__half2*>(&Ab[p][m][KX0 + rank * 32 + jl]);
            }
#pragma unroll
            for (int rr = 0; rr < 4; ++rr) {
                __half2* dst = (__half2*)cl.map_shared_rank(
                    (void*)&Ab[pn][m][KX0 + rank * 32 + jl], rr);
                *dst = hv;
            }
            *reinterpret_cast<__half2*>(
                &g_hs1[((size_t)t * BB + slotbase + m) * HH + rank * 32 + jl]) = hv;
        }
        cl.sync();
    }
}

// ---------------- K2: LSTM layer 1 ------------------------------------------------
// A = [h1_t(128) | h2(128)]  K=256, 16 k-tiles.
#define KX1 128
#define K1T 256
#define KT1 16

__global__ void __cluster_dims__(4, 1, 1) __launch_bounds__(256, 1)
lstm_l1(const float* __restrict__ Wih, const float* __restrict__ Whh,
        const float* __restrict__ bih, const float* __restrict__ bhh)
{
    cg::cluster_group cl = cg::this_cluster();
    const int rank  = (int)cl.block_rank();
    const int group = blockIdx.x >> 2;
    const int slotbase = group * 16;
    const int tid  = threadIdx.x;
    const int warp = tid >> 5, lane = tid & 31;

    __shared__ __half Ab[2][16][K1T];
    __shared__ float  gsm[16][128];
    __shared__ float  csm[16][32];
    __shared__ float  h2s[16][32];
    __shared__ float  bsm[128];
    __shared__ int    slenS[16];

    unsigned wf[2][KT1][2];
#pragma unroll
    for (int nt = 0; nt < 2; ++nt) {
        int n_local = warp * 16 + nt * 8 + (lane >> 2);
        int q = n_local >> 5, jj = n_local & 31;
        int grow = q * 128 + rank * 32 + jj;
#pragma unroll
        for (int kt = 0; kt < KT1; ++kt) {
#pragma unroll
            for (int f = 0; f < 2; ++f) {
                int k0 = kt * 16 + (lane & 3) * 2 + f * 8;
                int k1 = k0 + 1;
                float v0 = (k0 < KX1) ? Wih[grow * HH + k0] : Whh[grow * HH + (k0 - KX1)];
                float v1 = (k1 < KX1) ? Wih[grow * HH + k1] : Whh[grow * HH + (k1 - KX1)];
                __half2 hv = __floats2half2_rn(v0, v1);
                wf[nt][kt][f] = *reinterpret_cast<unsigned*>(&hv);
            }
        }
    }
    if (tid < 128) {
        int q = tid >> 5, jj = tid & 31;
        int grow = q * 128 + rank * 32 + jj;
        bsm[tid] = bih[grow] + bhh[grow];
    }
    if (tid < 16) slenS[tid] = g_slen[slotbase + tid];
    for (int i = tid; i < 2 * 16 * K1T; i += 256) ((__half*)Ab)[i] = __float2half(0.0f);
    for (int i = tid; i < 16 * 32;      i += 256) { ((float*)csm)[i] = 0.0f; ((float*)h2s)[i] = 0.0f; }
    __syncthreads();
    const int maxlen = slenS[0];
    // h1(0) -> buf 0  (16*128 halves, contiguous in g_hs1)
    {
        int i = tid * 8;
        int m = i >> 7, k = i & 127;
        uint4 v = *reinterpret_cast<const uint4*>(&g_hs1[((size_t)0 * BB + slotbase) * HH + i]);
        *reinterpret_cast<uint4*>(&Ab[0][m][k]) = v;
    }
    cl.sync();

    for (int t = 0; t < maxlen; ++t) {
        const int p = t & 1, pn = p ^ 1;
        if (t + 1 < maxlen) {
            int i = tid * 8;
            int m = i >> 7, k = i & 127;
            uint4 v = *reinterpret_cast<const uint4*>(
                &g_hs1[((size_t)(t + 1) * BB + slotbase) * HH + i]);
            *reinterpret_cast<uint4*>(&Ab[pn][m][k]) = v;
        }
        float acc[2][4];
        {
            int cb0 = warp * 16 + (lane & 3) * 2;
#pragma unroll
            for (int nt = 0; nt < 2; ++nt) {
                float b0 = bsm[cb0 + nt * 8], b1 = bsm[cb0 + nt * 8 + 1];
                acc[nt][0] = b0; acc[nt][1] = b1; acc[nt][2] = b0; acc[nt][3] = b1;
            }
#pragma unroll
            for (int kt = 0; kt < KT1; ++kt) {
                unsigned a[4];
                ldsmx4(a, &Ab[p][lane & 15][kt * 16 + ((lane >> 4) << 3)]);
                mma16816(acc[0], a, wf[0][kt]);
                mma16816(acc[1], a, wf[1][kt]);
            }
            int r0 = lane >> 2;
#pragma unroll
            for (int nt = 0; nt < 2; ++nt) {
                int c0 = warp * 16 + nt * 8 + (lane & 3) * 2;
                gsm[r0][c0]     = acc[nt][0]; gsm[r0][c0 + 1]     = acc[nt][1];
                gsm[r0 + 8][c0] = acc[nt][2]; gsm[r0 + 8][c0 + 1] = acc[nt][3];
            }
        }
        __syncthreads();
        {
            int m = tid >> 4, jl = (tid & 15) * 2;
            bool act = (t < slenS[m]);
            __half2 hv;
            if (act) {
                float i0 = sigf(gsm[m][jl]),        i1 = sigf(gsm[m][jl + 1]);
                float f0 = sigf(gsm[m][32 + jl]),   f1 = sigf(gsm[m][32 + jl + 1]);
                float q0 = tanhfa(gsm[m][64 + jl]), q1 = tanhfa(gsm[m][64 + jl + 1]);
                float o0 = sigf(gsm[m][96 + jl]),   o1 = sigf(gsm[m][96 + jl + 1]);
                float c0 = f0 * csm[m][jl]     + i0 * q0;
                float c1 = f1 * csm[m][jl + 1] + i1 * q1;
                csm[m][jl] = c0; csm[m][jl + 1] = c1;
                float h0 = o0 * tanhfa(c0), h1 = o1 * tanhfa(c1);
                h2s[m][jl] = h0; h2s[m][jl + 1] = h1;
                hv = __floats2half2_rn(h0, h1);
            } else {
                hv = *reinterpret_cast<__half2*>(&Ab[p][m][KX1 + rank * 32 + jl]);
            }
#pragma unroll
            for (int rr = 0; rr < 4; ++rr) {
                __half2* dst = (__half2*)cl.map_shared_rank(
                    (void*)&Ab[pn][m][KX1 + rank * 32 + jl], rr);
                *dst = hv;
            }
        }
        cl.sync();
    }
    // write fp32 final h2 slice
    {
        int m = tid >> 4, jl = (tid & 15) * 2;
        g_h2[(slotbase + m) * HH + rank * 32 + jl]     = h2s[m][jl];
        g_h2[(slotbase + m) * HH + rank * 32 + jl + 1] = h2s[m][jl + 1];
    }
}

// ---------------- K3: LayerNorm + Linear head ------------------------------------
__global__ void head_kernel(const float* __restrict__ lng, const float* __restrict__ lnb,
                            const float* __restrict__ fw, const float* __restrict__ fb,
                            float* __restrict__ out)
{
    int gm = blockIdx.x;
    int tid = threadIdx.x;       // 128 threads
    int bidx = g_order[gm];
    float v = g_h2[gm * HH + tid];
    float s = v, s2 = v * v;
#pragma unroll
    for (int o = 16; o; o >>= 1) {
        s  += __shfl_xor_sync(0xffffffffu, s, o);
        s2 += __shfl_xor_sync(0xffffffffu, s2, o);
    }
    __shared__ float rs[4], rs2[4], hn[HH];
    if ((tid & 31) == 0) { rs[tid >> 5] = s; rs2[tid >> 5] = s2; }
    __syncthreads();
    float mu  = (rs[0] + rs[1] + rs[2] + rs[3]) * (1.0f / HH);
    float var = (rs2[0] + rs2[1] + rs2[2] + rs2[3]) * (1.0f / HH) - mu * mu;
    hn[tid] = (v - mu) * rsqrtf(var + 1e-5f) * lng[tid] + lnb[tid];
    __syncthreads();
    if (tid < CC) {
        float acc = fb[tid];
#pragma unroll 8
        for (int j = 0; j < HH; ++j) acc += fw[tid * HH + j] * hn[j];
        out[bidx * CC + tid] = acc;
    }
}

// ---------------- launch ----------------------------------------------------------
extern "C" void kernel_launch(void* const* d_in, const int* in_sizes, int n_in,
                              void* d_out, int out_size)
{
    (void)in_sizes; (void)n_in; (void)out_size;
    const float* x     = (const float*)d_in[0];
    const int*   len   = (const int*)  d_in[1];
    const float* Wih0  = (const float*)d_in[2];
    const float* Whh0  = (const float*)d_in[3];
    const float* bih0  = (const float*)d_in[4];
    const float* bhh0  = (const float*)d_in[5];
    const float* Wih1  = (const float*)d_in[6];
    const float* Whh1  = (const float*)d_in[7];
    const float* bih1  = (const float*)d_in[8];
    const float* bhh1  = (const float*)d_in[9];
    const float* lng   = (const float*)d_in[10];
    const float* lnb   = (const float*)d_in[11];
    const float* fcw   = (const float*)d_in[12];
    const float* fcb   = (const float*)d_in[13];
    float* out = (float*)d_out;

    sort_kernel<<<1, BB>>>(len);
    lstm_l0<<<64, 256>>>(x, Wih0, Whh0, bih0, bhh0);
    lstm_l1<<<64, 256>>>(Wih1, Whh1, bih1, bhh1);
    head_kernel<<<BB, 128>>>(lng, lnb, fcw, fcb, out);
}

// round 4
// speedup vs baseline: 3.6976x; 3.6976x over previous
#include <cuda_runtime.h>
#include <cuda_fp16.h>
#include <cooperative_groups.h>

namespace cg = cooperative_groups;

#define BB 256
#define TT 2048
#define DD 40
#define HH 128
#define CC 35

// A-operand row layout (unified for both layers), padded for conflict-free ldmatrix:
// stride 264 halves = 528B; 528 mod 128 = 16 -> 8 consecutive rows hit distinct 16B banks.
#define AK 264
// layer0: A = [x(40) pad->48 | h1(128)]  K=176 -> 11 k-tiles
// layer1: A = [h1(128) | h2(128)]        K=256 -> 16 k-tiles
#define KT0 11
#define KT1 16

// ---------------- device scratch ----------------
__device__ int   g_order[BB];
__device__ int   g_slen[BB];
__device__ float g_h2[BB * HH];

// ---------------- helpers ----------------
__device__ __forceinline__ void mma16816(float* d, const unsigned* a, const unsigned* b) {
    asm volatile(
        "mma.sync.aligned.m16n8k16.row.col.f32.f16.f16.f32 "
        "{%0,%1,%2,%3}, {%4,%5,%6,%7}, {%8,%9}, {%0,%1,%2,%3};\n"
        : "+f"(d[0]), "+f"(d[1]), "+f"(d[2]), "+f"(d[3])
        : "r"(a[0]), "r"(a[1]), "r"(a[2]), "r"(a[3]), "r"(b[0]), "r"(b[1]));
}

__device__ __forceinline__ void ldsmx4(unsigned* a, const __half* p) {
    unsigned addr = (unsigned)__cvta_generic_to_shared(p);
    asm volatile("ldmatrix.sync.aligned.m8n8.x4.shared.b16 {%0,%1,%2,%3}, [%4];"
                 : "=r"(a[0]), "=r"(a[1]), "=r"(a[2]), "=r"(a[3])
                 : "r"(addr));
}

__device__ __forceinline__ float sigf(float x)   { return 1.0f / (1.0f + __expf(-x)); }
__device__ __forceinline__ float tanhfa(float x) { return 1.0f - 2.0f / (__expf(2.0f * x) + 1.0f); }

// ---------------- K0: rank-sort lengths (descending, stable) ----------------
__global__ void sort_kernel(const int* __restrict__ length) {
    __shared__ int len[BB];
    int i = threadIdx.x;
    len[i] = length[i];
    __syncthreads();
    int li = len[i];
    int rank = 0;
    for (int j = 0; j < BB; ++j) {
        int lj = len[j];
        rank += (lj > li) || (lj == li && j < i);
    }
    g_order[rank] = i;
    g_slen[rank]  = li;
}

// ---------------- K1: fused 2-layer LSTM ----------------
// 16 clusters of 8 CTAs. Ranks 0-3: layer 0 (gate-slice = rank). Ranks 4-7: layer 1,
// lagging one superstep. Each CTA: M=16 batch rows, N=128 gate columns, 256 threads.
// Gate-interleaved column map: n_local -> gate q = n&3, h-index j = (n>>2) + 32*lrank.
// Per superstep s:  l0 computes h1(s) (s<maxlen);  l1 computes h2(s-1) (s>=1).
// One cluster.sync per superstep. h/c state lives in registers.
__global__ void __cluster_dims__(8, 1, 1) __launch_bounds__(256, 1)
lstm_fused(const float* __restrict__ x,
           const float* __restrict__ Wih0, const float* __restrict__ Whh0,
           const float* __restrict__ bih0, const float* __restrict__ bhh0,
           const float* __restrict__ Wih1, const float* __restrict__ Whh1,
           const float* __restrict__ bih1, const float* __restrict__ bhh1)
{
    cg::cluster_group cl = cg::this_cluster();
    const int rank   = (int)cl.block_rank();
    const bool is_l0 = (rank < 4);
    const int lrank  = rank & 3;
    const int group  = blockIdx.x >> 3;
    const int slotbase = group * 16;
    const int tid  = threadIdx.x;
    const int warp = tid >> 5, lane = tid & 31;

    __shared__ __align__(16) __half Ab[2][16][AK];
    __shared__ __align__(16) __half hstage[16][32];
    __shared__ float bsm[128];
    __shared__ int   slenS[16], morder[16];

    // ---- weights -> register fragments (gate-interleaved columns) ----
    const float* Wih = is_l0 ? Wih0 : Wih1;
    const float* Whh = is_l0 ? Whh0 : Whh1;
    const float* bih = is_l0 ? bih0 : bih1;
    const float* bhh = is_l0 ? bhh0 : bhh1;
    const int KX  = is_l0 ? 48 : 128;   // boundary: ih part | hh part
    const int DIN = is_l0 ? DD : HH;    // valid ih columns

    unsigned wf[2][16][2];
#pragma unroll
    for (int nt = 0; nt < 2; ++nt) {
        int n_local = warp * 16 + nt * 8 + (lane >> 2);
        int grow = (n_local & 3) * 128 + lrank * 32 + (n_local >> 2);
        for (int kt = 0; kt < 16; ++kt) {
            if (kt >= (is_l0 ? KT0 : KT1)) break;
#pragma unroll
            for (int f = 0; f < 2; ++f) {
                int k0 = kt * 16 + (lane & 3) * 2 + f * 8;
                int k1 = k0 + 1;
                float v0 = (k0 < KX) ? ((k0 < DIN) ? Wih[grow * DIN + k0] : 0.0f)
                                     : Whh[grow * HH + (k0 - KX)];
                float v1 = (k1 < KX) ? ((k1 < DIN) ? Wih[grow * DIN + k1] : 0.0f)
                                     : Whh[grow * HH + (k1 - KX)];
                __half2 hv = __floats2half2_rn(v0, v1);
                wf[nt][kt][f] = *reinterpret_cast<unsigned*>(&hv);
            }
        }
    }
    if (tid < 128) {
        int grow = (tid & 3) * 128 + lrank * 32 + (tid >> 2);
        bsm[tid] = bih[grow] + bhh[grow];
    }
    if (tid < 16) {
        slenS[tid]  = g_slen[slotbase + tid];
        morder[tid] = g_order[slotbase + tid];
    }
    for (int i = tid; i < 2 * 16 * AK; i += 256) ((__half*)Ab)[i] = __float2half(0.0f);
    __syncthreads();
    const int maxlen = slenS[0];

    // per-thread cell ownership: row and 2 h-indices (one per n-tile)
    const int m_row = (lane >> 2) + ((lane & 1) << 3);
    const int myslen = slenS[m_row];
    const int hj0 = (warp << 2) + ((lane & 3) >> 1);
    const int hj1 = hj0 + 2;
    float creg[2] = {0.0f, 0.0f};
    float hreg[2] = {0.0f, 0.0f};

    // x(0) -> buffer 0 (layer-0 CTAs)
    if (is_l0) {
        for (int i = tid; i < 16 * DD; i += 256) {
            int m = i / DD, d = i - m * DD;
            Ab[0][m][d] = __float2half(x[((size_t)morder[m] * TT) * DD + d]);
        }
    }
    cl.sync();

    for (int s = 0; s <= maxlen; ++s) {
        const int p = s & 1, pn = p ^ 1;
        const bool compute = is_l0 ? (s < maxlen) : (s >= 1);

        // ---- x(s+1) prefetch into registers (store deferred past MMA) ----
        float xv0 = 0.0f, xv1 = 0.0f, xv2 = 0.0f;
        const bool do_pref = is_l0 && (s + 1 < maxlen);
        if (do_pref) {
            int i0 = tid, i1 = tid + 256, i2 = tid + 512;
            {
                int m = i0 / DD, d = i0 - m * DD;
                xv0 = x[((size_t)morder[m] * TT + (s + 1)) * DD + d];
            }
            {
                int m = i1 / DD, d = i1 - m * DD;
                xv1 = x[((size_t)morder[m] * TT + (s + 1)) * DD + d];
            }
            if (i2 < 16 * DD) {
                int m = i2 / DD, d = i2 - m * DD;
                xv2 = x[((size_t)morder[m] * TT + (s + 1)) * DD + d];
            }
        }

        if (compute) {
            // ---- MMA ----
            float acc[2][4];
            int cb0 = warp * 16 + 2 * (lane & 3);
#pragma unroll
            for (int nt = 0; nt < 2; ++nt) {
                float b0 = bsm[cb0 + nt * 8], b1 = bsm[cb0 + nt * 8 + 1];
                acc[nt][0] = b0; acc[nt][1] = b1; acc[nt][2] = b0; acc[nt][3] = b1;
            }
            const __half* arow = &Ab[p][lane & 15][(lane >> 4) << 3];
            if (is_l0) {
#pragma unroll
                for (int kt = 0; kt < KT0; ++kt) {
                    unsigned a[4];
                    ldsmx4(a, arow + kt * 16);
                    mma16816(acc[0], a, wf[0][kt]);
                    mma16816(acc[1], a, wf[1][kt]);
                }
            } else {
#pragma unroll
                for (int kt = 0; kt < KT1; ++kt) {
                    unsigned a[4];
                    ldsmx4(a, arow + kt * 16);
                    mma16816(acc[0], a, wf[0][kt]);
                    mma16816(acc[1], a, wf[1][kt]);
                }
            }

            // ---- pair exchange + register pointwise ----
            const int t_eff = is_l0 ? s : (s - 1);
            const bool act = t_eff < myslen;
            const int sel = (lane & 1) * 2;
#pragma unroll
            for (int nt = 0; nt < 2; ++nt) {
                float o0 = __shfl_xor_sync(0xffffffffu, acc[nt][0], 1);
                float o1 = __shfl_xor_sync(0xffffffffu, acc[nt][1], 1);
                float o2 = __shfl_xor_sync(0xffffffffu, acc[nt][2], 1);
                float o3 = __shfl_xor_sync(0xffffffffu, acc[nt][3], 1);
                // lane&1==0 holds gates (i,f); lane&1==1 holds gates (g,o)
                float iv, fv, gv, ov;
                if ((lane & 1) == 0) {
                    iv = acc[nt][sel]; fv = acc[nt][sel + 1];
                    gv = (sel == 0) ? o0 : o2; ov = (sel == 0) ? o1 : o3;
                } else {
                    iv = (sel == 0) ? o0 : o2; fv = (sel == 0) ? o1 : o3;
                    gv = acc[nt][sel]; ov = acc[nt][sel + 1];
                }
                float hn;
                if (act) {
                    float gi = sigf(iv), gf = sigf(fv), gg = tanhfa(gv), go = sigf(ov);
                    float cn = gf * creg[nt] + gi * gg;
                    creg[nt] = cn;
                    hn = go * tanhfa(cn);
                    hreg[nt] = hn;
                } else {
                    hn = hreg[nt];
                }
                hstage[m_row][nt ? hj1 : hj0] = __float2half(hn);
            }
        }

        // deferred x store (own SMEM, read only next superstep)
        if (do_pref) {
            int i0 = tid, i1 = tid + 256, i2 = tid + 512;
            Ab[pn][i0 / DD][i0 % DD] = __float2half(xv0);
            Ab[pn][i1 / DD][i1 % DD] = __float2half(xv1);
            if (i2 < 16 * DD) Ab[pn][i2 / DD][i2 % DD] = __float2half(xv2);
        }
        __syncthreads();

        // ---- broadcast h slice to consumer CTAs (warp w -> rank w) ----
        // l0 producer: all 8 ranks need h1 (l0 at col 48+32*lrank, l1 at col 32*lrank)
        // l1 producer: ranks 4-7 need h2 at col 128+32*lrank
        if (compute && (is_l0 || warp >= 4)) {
            int doff = (warp < 4) ? (48 + lrank * 32)
                                  : ((is_l0 ? 0 : 128) + lrank * 32);
#pragma unroll
            for (int k2 = 0; k2 < 2; ++k2) {
                int chunk = k2 * 32 + lane;
                int row = chunk >> 2, c4 = chunk & 3;
                uint4 v = *reinterpret_cast<const uint4*>(&hstage[row][c4 * 8]);
                uint4* dst = (uint4*)cl.map_shared_rank(
                    (void*)&Ab[pn][row][doff + c4 * 8], warp);
                *dst = v;
            }
        }
        cl.sync();
    }

    // ---- final h2 (fp32) from layer-1 CTAs ----
    if (!is_l0) {
        int hb = lrank * 32;
        g_h2[(slotbase + m_row) * HH + hb + hj0] = hreg[0];
        g_h2[(slotbase + m_row) * HH + hb + hj1] = hreg[1];
    }
}

// ---------------- K3: LayerNorm + Linear head ----------------
__global__ void head_kernel(const float* __restrict__ lng, const float* __restrict__ lnb,
                            const float* __restrict__ fw, const float* __restrict__ fb,
                            float* __restrict__ out)
{
    int gm = blockIdx.x;
    int tid = threadIdx.x;       // 128 threads
    int bidx = g_order[gm];
    float v = g_h2[gm * HH + tid];
    float s = v, s2 = v * v;
#pragma unroll
    for (int o = 16; o; o >>= 1) {
        s  += __shfl_xor_sync(0xffffffffu, s, o);
        s2 += __shfl_xor_sync(0xffffffffu, s2, o);
    }
    __shared__ float rs[4], rs2[4], hn[HH];
    if ((tid & 31) == 0) { rs[tid >> 5] = s; rs2[tid >> 5] = s2; }
    __syncthreads();
    float mu  = (rs[0] + rs[1] + rs[2] + rs[3]) * (1.0f / HH);
    float var = (rs2[0] + rs2[1] + rs2[2] + rs2[3]) * (1.0f / HH) - mu * mu;
    hn[tid] = (v - mu) * rsqrtf(var + 1e-5f) * lng[tid] + lnb[tid];
    __syncthreads();
    if (tid < CC) {
        float acc = fb[tid];
#pragma unroll 8
        for (int j = 0; j < HH; ++j) acc += fw[tid * HH + j] * hn[j];
        out[bidx * CC + tid] = acc;
    }
}

// ---------------- launch ----------------
extern "C" void kernel_launch(void* const* d_in, const int* in_sizes, int n_in,
                              void* d_out, int out_size)
{
    (void)in_sizes; (void)n_in; (void)out_size;
    const float* x     = (const float*)d_in[0];
    const int*   len   = (const int*)  d_in[1];
    const float* Wih0  = (const float*)d_in[2];
    const float* Whh0  = (const float*)d_in[3];
    const float* bih0  = (const float*)d_in[4];
    const float* bhh0  = (const float*)d_in[5];
    const float* Wih1  = (const float*)d_in[6];
    const float* Whh1  = (const float*)d_in[7];
    const float* bih1  = (const float*)d_in[8];
    const float* bhh1  = (const float*)d_in[9];
    const float* lng   = (const float*)d_in[10];
    const float* lnb   = (const float*)d_in[11];
    const float* fcw   = (const float*)d_in[12];
    const float* fcb   = (const float*)d_in[13];
    float* out = (float*)d_out;

    sort_kernel<<<1, BB>>>(len);
    lstm_fused<<<128, 256>>>(x, Wih0, Whh0, bih0, bhh0, Wih1, Whh1, bih1, bhh1);
    head_kernel<<<BB, 128>>>(lng, lnb, fcw, fcb, out);
}